// round 1
// baseline (speedup 1.0000x reference)
#include <cuda_runtime.h>
#include <math.h>

#define B_    64
#define T_    512
#define F_    64
#define H_    512
#define G_    2048          // 4*H
#define M_    (B_*T_)       // 32768
#define NCTA_ 128

// ---------------- scratch (static device allocations only) ----------------
__device__ float g_xT[(size_t)F_ * M_];       //   8 MB : x transposed [F][M]
__device__ float g_xw[(size_t)M_ * G_];       // 256 MB : xW (+bias) [M][G], reused by both layers
__device__ float g_hseqT[(size_t)H_ * M_];    //  64 MB : layer-1 output transposed [H][M]
__device__ float g_hbufT[2 * H_ * B_];        // double-buffered h state, transposed [H][B]
__device__ unsigned g_bar_count;
__device__ unsigned g_bar_gen;

// ---------------- grid-wide barrier (all CTAs co-resident) ----------------
__device__ __forceinline__ void grid_barrier()
{
    __syncthreads();
    if (threadIdx.x == 0) {
        const unsigned nb = gridDim.x;
        __threadfence();
        unsigned gen = atomicAdd(&g_bar_gen, 0u);
        __threadfence();
        unsigned arrived = atomicAdd(&g_bar_count, 1u);
        if (arrived == nb - 1u) {
            atomicExch(&g_bar_count, 0u);
            __threadfence();
            atomicAdd(&g_bar_gen, 1u);
        } else {
            while (atomicAdd(&g_bar_gen, 0u) == gen) { __nanosleep(64); }
        }
        __threadfence();
    }
    __syncthreads();
}

// ---------------- x transpose: x[M][F] -> xT[F][M] ----------------
__global__ void __launch_bounds__(256) transpose_x(const float* __restrict__ x,
                                                   float* __restrict__ xT)
{
    __shared__ float tile[32][33];
    const int m0 = blockIdx.x * 32;
    const int f0 = blockIdx.y * 32;
    const int tx = threadIdx.x, ty = threadIdx.y;
#pragma unroll
    for (int i = 0; i < 32; i += 8)
        tile[ty + i][tx] = x[(size_t)(m0 + ty + i) * F_ + f0 + tx];
    __syncthreads();
#pragma unroll
    for (int i = 0; i < 32; i += 8)
        xT[(size_t)(f0 + ty + i) * M_ + m0 + tx] = tile[tx][ty + i];
}

// ---------------- GEMM: C[M][N] = AT^T @ B + bias ----------------
// AT: [K][M] (row-major), Bm: [K][N], bias: [N]. BM=BN=64, BK=16, 256 thr, 4x4 micro.
__global__ void __launch_bounds__(256) gemm_atb(const float* __restrict__ AT,
                                                const float* __restrict__ Bm,
                                                const float* __restrict__ bias,
                                                float* __restrict__ C,
                                                int M, int N, int K)
{
    __shared__ float As[2][16 * 64];
    __shared__ float Bs[2][16 * 64];
    const int tid = threadIdx.x;
    const int tx = tid & 15, ty = tid >> 4;
    const int m0 = blockIdx.y * 64, n0 = blockIdx.x * 64;
    const int lr = tid >> 4, lc4 = (tid & 15) * 4;

    const float* ap = AT + (size_t)lr * M + m0 + lc4;
    const float* bp = Bm + (size_t)lr * N + n0 + lc4;
    float4 aReg = *(const float4*)ap;
    float4 bReg = *(const float4*)bp;

    float acc[4][4];
#pragma unroll
    for (int i = 0; i < 4; i++)
#pragma unroll
        for (int j = 0; j < 4; j++) acc[i][j] = 0.f;

    const int NT = K >> 4;
    for (int kt = 0; kt < NT; kt++) {
        const int cur = kt & 1;
        *(float4*)&As[cur][lr * 64 + lc4] = aReg;
        *(float4*)&Bs[cur][lr * 64 + lc4] = bReg;
        __syncthreads();
        if (kt + 1 < NT) {
            aReg = *(const float4*)(ap + (size_t)(kt + 1) * 16 * M);
            bReg = *(const float4*)(bp + (size_t)(kt + 1) * 16 * N);
        }
#pragma unroll
        for (int kk = 0; kk < 16; kk++) {
            float4 a = *(const float4*)&As[cur][kk * 64 + ty * 4];
            float4 b = *(const float4*)&Bs[cur][kk * 64 + tx * 4];
            acc[0][0] = fmaf(a.x, b.x, acc[0][0]);
            acc[0][1] = fmaf(a.x, b.y, acc[0][1]);
            acc[0][2] = fmaf(a.x, b.z, acc[0][2]);
            acc[0][3] = fmaf(a.x, b.w, acc[0][3]);
            acc[1][0] = fmaf(a.y, b.x, acc[1][0]);
            acc[1][1] = fmaf(a.y, b.y, acc[1][1]);
            acc[1][2] = fmaf(a.y, b.z, acc[1][2]);
            acc[1][3] = fmaf(a.y, b.w, acc[1][3]);
            acc[2][0] = fmaf(a.z, b.x, acc[2][0]);
            acc[2][1] = fmaf(a.z, b.y, acc[2][1]);
            acc[2][2] = fmaf(a.z, b.z, acc[2][2]);
            acc[2][3] = fmaf(a.z, b.w, acc[2][3]);
            acc[3][0] = fmaf(a.w, b.x, acc[3][0]);
            acc[3][1] = fmaf(a.w, b.y, acc[3][1]);
            acc[3][2] = fmaf(a.w, b.z, acc[3][2]);
            acc[3][3] = fmaf(a.w, b.w, acc[3][3]);
        }
    }
    float4 bv = *(const float4*)(bias + n0 + tx * 4);
#pragma unroll
    for (int i = 0; i < 4; i++) {
        float4 o;
        o.x = acc[i][0] + bv.x;
        o.y = acc[i][1] + bv.y;
        o.z = acc[i][2] + bv.z;
        o.w = acc[i][3] + bv.w;
        *(float4*)&C[(size_t)(m0 + ty * 4 + i) * N + n0 + tx * 4] = o;
    }
}

// ---------------- persistent LSTM layer ----------------
// 128 CTAs, each owns 4 hidden cols (16 gate cols). z = xw[:,t,:] + h@Wh.
// SMEM: h_s[512][64] staged per step, w_s[512][16] loaded once, c state persistent.
__global__ void __launch_bounds__(256, 1) lstm_persistent(const float* __restrict__ xw,
                                                          const float* __restrict__ Wh,
                                                          float* __restrict__ hseqT)
{
    extern __shared__ float sm[];
    float* h_s = sm;                 // 512*64 = 32768
    float* w_s = sm + 32768;         // 512*16 =  8192
    float* red = w_s + 8192;         // 3*64*16 = 3072
    float* z_s = red + 3072;         // 64*16  =  1024
    float* c_s = z_s + 1024;         // 64*4   =   256

    const int tid = threadIdx.x;
    const int hc0 = blockIdx.x * 4;

    // load Wh slice: w_s[k][g*4+c] = Wh[k][g*512 + hc0 + c]
    for (int i = tid; i < 512 * 4; i += 256) {
        int k = i >> 2, g = i & 3;
        *(float4*)(w_s + k * 16 + g * 4) =
            *(const float4*)(Wh + (size_t)k * G_ + g * H_ + hc0);
    }
    c_s[tid] = 0.f;
    {   // zero h buf0 (this CTA's slice)
        int c = tid >> 6, b = tid & 63;
        g_hbufT[(hc0 + c) * B_ + b] = 0.f;
    }
    __threadfence();
    grid_barrier();

    const int q  = tid >> 6;   // k-split group (K range [q*128, q*128+128))
    const int r  = tid & 63;
    const int rg = r & 15;     // rows 4*rg .. 4*rg+3
    const int cg = r >> 4;     // gate index 0..3 (tile cols 4*cg..4*cg+3)

    for (int t = 0; t < T_; t++) {
        const float* hsrc = g_hbufT + (t & 1) * (H_ * B_);
        float*       hdst = g_hbufT + ((t & 1) ^ 1) * (H_ * B_);

        // stage full h (transposed: h_s[k][b]) from global
        for (int i = tid; i < (H_ * B_) / 4; i += 256)
            ((float4*)h_s)[i] = ((const float4*)hsrc)[i];

        // prefetch xw for this step (q==0 threads only)
        float4 xv0, xv1, xv2, xv3;
        if (q == 0) {
            const float* xp = xw + (size_t)(4 * rg * T_ + t) * G_ + cg * H_ + hc0;
            xv0 = *(const float4*)(xp);
            xv1 = *(const float4*)(xp + (size_t)T_ * G_);
            xv2 = *(const float4*)(xp + (size_t)2 * T_ * G_);
            xv3 = *(const float4*)(xp + (size_t)3 * T_ * G_);
        }
        __syncthreads();

        float acc[4][4];
#pragma unroll
        for (int i = 0; i < 4; i++)
#pragma unroll
            for (int j = 0; j < 4; j++) acc[i][j] = 0.f;

        const float* hp = h_s + q * 128 * 64 + 4 * rg;
        const float* wp = w_s + q * 128 * 16 + 4 * cg;
#pragma unroll 8
        for (int kk = 0; kk < 128; kk++) {
            float4 hv = *(const float4*)(hp + kk * 64);
            float4 wv = *(const float4*)(wp + kk * 16);
            acc[0][0] = fmaf(hv.x, wv.x, acc[0][0]);
            acc[0][1] = fmaf(hv.x, wv.y, acc[0][1]);
            acc[0][2] = fmaf(hv.x, wv.z, acc[0][2]);
            acc[0][3] = fmaf(hv.x, wv.w, acc[0][3]);
            acc[1][0] = fmaf(hv.y, wv.x, acc[1][0]);
            acc[1][1] = fmaf(hv.y, wv.y, acc[1][1]);
            acc[1][2] = fmaf(hv.y, wv.z, acc[1][2]);
            acc[1][3] = fmaf(hv.y, wv.w, acc[1][3]);
            acc[2][0] = fmaf(hv.z, wv.x, acc[2][0]);
            acc[2][1] = fmaf(hv.z, wv.y, acc[2][1]);
            acc[2][2] = fmaf(hv.z, wv.z, acc[2][2]);
            acc[2][3] = fmaf(hv.z, wv.w, acc[2][3]);
            acc[3][0] = fmaf(hv.w, wv.x, acc[3][0]);
            acc[3][1] = fmaf(hv.w, wv.y, acc[3][1]);
            acc[3][2] = fmaf(hv.w, wv.z, acc[3][2]);
            acc[3][3] = fmaf(hv.w, wv.w, acc[3][3]);
        }

        if (q) {
            float* rp = red + ((q - 1) * 64 + r) * 16;
#pragma unroll
            for (int i = 0; i < 4; i++)
#pragma unroll
                for (int j = 0; j < 4; j++) rp[i * 4 + j] = acc[i][j];
        }
        __syncthreads();

        if (q == 0) {
#pragma unroll
            for (int qq = 0; qq < 3; qq++) {
                const float* rp = red + (qq * 64 + r) * 16;
#pragma unroll
                for (int i = 0; i < 4; i++)
#pragma unroll
                    for (int j = 0; j < 4; j++) acc[i][j] += rp[i * 4 + j];
            }
            float4 xv[4] = {xv0, xv1, xv2, xv3};
#pragma unroll
            for (int i = 0; i < 4; i++) {
                const float* xf = (const float*)&xv[i];
#pragma unroll
                for (int j = 0; j < 4; j++)
                    z_s[(4 * rg + i) * 16 + 4 * cg + j] = acc[i][j] + xf[j];
            }
        }
        __syncthreads();

        // state update: thread -> (b = tid>>2, c = tid&3)
        {
            const int b = tid >> 2, c = tid & 3;
            float zi = z_s[b * 16 + 0  + c];
            float zf = z_s[b * 16 + 4  + c];
            float zg = z_s[b * 16 + 8  + c];
            float zo = z_s[b * 16 + 12 + c];
            float ig = 1.f / (1.f + expf(-zi));
            float fg = 1.f / (1.f + expf(-zf));
            float gg = tanhf(zg);
            float og = 1.f / (1.f + expf(-zo));
            float cc = fmaf(fg, c_s[tid], ig * gg);
            c_s[tid] = cc;
            float hh = og * tanhf(cc);
            hdst[(hc0 + c) * B_ + b] = hh;
            if (hseqT)
                hseqT[(size_t)(hc0 + c) * M_ + b * T_ + t] = hh;
        }
        __threadfence();
        grid_barrier();
    }
}

// ---------------- head: out[b] = relu(relu(h@Wd1 + bd1) @ Wd2 + bd2) ----------------
__global__ void __launch_bounds__(256) head_kernel(const float* __restrict__ Wd1,
                                                   const float* __restrict__ bd1,
                                                   const float* __restrict__ Wd2,
                                                   const float* __restrict__ bd2,
                                                   float* __restrict__ out)
{
    const int b = blockIdx.x;
    const int j = threadIdx.x;                 // 0..255
    const float* hT = g_hbufT;                 // final h lives in buf0 (t=511 writes buf0)
    float acc = 0.f;
#pragma unroll 8
    for (int k = 0; k < H_; k++)
        acc = fmaf(hT[k * B_ + b], Wd1[k * (H_ / 2) + j], acc);
    float t1 = fmaxf(acc + bd1[j], 0.f);
    float p  = t1 * Wd2[j];
    __shared__ float s[256];
    s[j] = p;
    __syncthreads();
    for (int off = 128; off; off >>= 1) {
        if (j < off) s[j] += s[j + off];
        __syncthreads();
    }
    if (j == 0) out[b] = fmaxf(s[0] + bd2[0], 0.f);
}

// ---------------- launch ----------------
extern "C" void kernel_launch(void* const* d_in, const int* in_sizes, int n_in,
                              void* d_out, int out_size)
{
    (void)in_sizes; (void)n_in; (void)out_size;
    const float* x   = (const float*)d_in[0];
    // d_in[1] = training (unused)
    const float* Wi1 = (const float*)d_in[2];
    const float* Wh1 = (const float*)d_in[3];
    const float* b1  = (const float*)d_in[4];
    const float* Wi2 = (const float*)d_in[5];
    const float* Wh2 = (const float*)d_in[6];
    const float* b2  = (const float*)d_in[7];
    const float* Wd1 = (const float*)d_in[8];
    const float* bd1 = (const float*)d_in[9];
    const float* Wd2 = (const float*)d_in[10];
    const float* bd2 = (const float*)d_in[11];
    float* out = (float*)d_out;

    float *xT, *xwb, *hseqT;
    cudaGetSymbolAddress((void**)&xT,    g_xT);
    cudaGetSymbolAddress((void**)&xwb,   g_xw);
    cudaGetSymbolAddress((void**)&hseqT, g_hseqT);

    const size_t smem = (32768 + 8192 + 3072 + 1024 + 256) * sizeof(float); // 181248 B
    cudaFuncSetAttribute(lstm_persistent,
                         cudaFuncAttributeMaxDynamicSharedMemorySize, (int)smem);

    transpose_x<<<dim3(1024, 2), dim3(32, 8)>>>(x, xT);
    gemm_atb<<<dim3(G_ / 64, M_ / 64), 256>>>(xT, Wi1, b1, xwb, M_, G_, F_);
    lstm_persistent<<<NCTA_, 256, smem>>>(xwb, Wh1, hseqT);
    gemm_atb<<<dim3(G_ / 64, M_ / 64), 256>>>(hseqT, Wi2, b2, xwb, M_, G_, H_);
    lstm_persistent<<<NCTA_, 256, smem>>>(xwb, Wh2, nullptr);
    head_kernel<<<B_, 256>>>(Wd1, bd1, Wd2, bd2, out);
}

// round 4
// speedup vs baseline: 1.0271x; 1.0271x over previous
#include <cuda_runtime.h>
#include <math.h>

#define B_    64
#define T_    512
#define F_    64
#define H_    512
#define G_    2048          // 4*H
#define M_    (B_*T_)       // 32768
#define NCTA_ 128

typedef unsigned long long ull;

// ---------------- packed f32x2 helpers ----------------
__device__ __forceinline__ void ffma2(ull& acc, ull a, ull b) {
    asm("fma.rn.f32x2 %0, %1, %2, %0;" : "+l"(acc) : "l"(a), "l"(b));
}
__device__ __forceinline__ ull pack2(float lo, float hi) {
    ull r; asm("mov.b64 %0, {%1, %2};" : "=l"(r) : "f"(lo), "f"(hi)); return r;
}
__device__ __forceinline__ void unpack2(ull v, float& lo, float& hi) {
    asm("mov.b64 {%0, %1}, %2;" : "=f"(lo), "=f"(hi) : "l"(v));
}

// ---------------- scratch (static device allocations only) ----------------
__device__ float g_xT[(size_t)F_ * M_];       //   8 MB : x transposed [F][M]
__device__ float g_xw[(size_t)M_ * G_];       // 256 MB : xW (+bias) [M][G], reused by both layers
__device__ float g_hseqT[(size_t)H_ * M_];    //  64 MB : layer-1 output transposed [H][M]
__device__ float g_hbufT[2 * H_ * B_];        // double-buffered h state, transposed [H][B]
__device__ unsigned g_bar_count;
__device__ unsigned g_bar_gen;

// ---------------- grid-wide barrier (round-1 proven version) ----------------
__device__ __forceinline__ void grid_barrier()
{
    __syncthreads();
    if (threadIdx.x == 0) {
        const unsigned nb = gridDim.x;
        __threadfence();
        unsigned gen = atomicAdd(&g_bar_gen, 0u);
        __threadfence();
        unsigned arrived = atomicAdd(&g_bar_count, 1u);
        if (arrived == nb - 1u) {
            atomicExch(&g_bar_count, 0u);
            __threadfence();
            atomicAdd(&g_bar_gen, 1u);
        } else {
            while (atomicAdd(&g_bar_gen, 0u) == gen) { __nanosleep(64); }
        }
        __threadfence();
    }
    __syncthreads();
}

// ---------------- x transpose: x[M][F] -> xT[F][M] ----------------
__global__ void __launch_bounds__(256) transpose_x(const float* __restrict__ x,
                                                   float* __restrict__ xT)
{
    __shared__ float tile[32][33];
    const int m0 = blockIdx.x * 32;
    const int f0 = blockIdx.y * 32;
    const int tx = threadIdx.x, ty = threadIdx.y;
#pragma unroll
    for (int i = 0; i < 32; i += 8)
        tile[ty + i][tx] = x[(size_t)(m0 + ty + i) * F_ + f0 + tx];
    __syncthreads();
#pragma unroll
    for (int i = 0; i < 32; i += 8)
        xT[(size_t)(f0 + ty + i) * M_ + m0 + tx] = tile[tx][ty + i];
}

// ---------------- GEMM: C[M][N] = AT^T @ B + bias ----------------
// AT: [K][M] (row-major), Bm: [K][N], bias: [N]. BM=BN=64, BK=16, 256 thr, 4x4 micro.
// Round-1 structure; inner loop uses fma.rn.f32x2 (the ONLY delta).
__global__ void __launch_bounds__(256) gemm_atb(const float* __restrict__ AT,
                                                const float* __restrict__ Bm,
                                                const float* __restrict__ bias,
                                                float* __restrict__ C,
                                                int M, int N, int K)
{
    __shared__ float As[2][16 * 64];
    __shared__ float Bs[2][16 * 64];
    const int tid = threadIdx.x;
    const int tx = tid & 15, ty = tid >> 4;
    const int m0 = blockIdx.y * 64, n0 = blockIdx.x * 64;
    const int lr = tid >> 4, lc4 = (tid & 15) * 4;

    const float* ap = AT + (size_t)lr * M + m0 + lc4;
    const float* bp = Bm + (size_t)lr * N + n0 + lc4;
    float4 aReg = *(const float4*)ap;
    float4 bReg = *(const float4*)bp;

    ull accP[4][2];
#pragma unroll
    for (int i = 0; i < 4; i++) { accP[i][0] = 0ull; accP[i][1] = 0ull; }

    const int NT = K >> 4;
    for (int kt = 0; kt < NT; kt++) {
        const int cur = kt & 1;
        *(float4*)&As[cur][lr * 64 + lc4] = aReg;
        *(float4*)&Bs[cur][lr * 64 + lc4] = bReg;
        __syncthreads();
        if (kt + 1 < NT) {
            aReg = *(const float4*)(ap + (size_t)(kt + 1) * 16 * M);
            bReg = *(const float4*)(bp + (size_t)(kt + 1) * 16 * N);
        }
#pragma unroll
        for (int kk = 0; kk < 16; kk++) {
            float4 a = *(const float4*)&As[cur][kk * 64 + ty * 4];
            ulonglong2 bv = *(const ulonglong2*)&Bs[cur][kk * 64 + tx * 4];
            ull a0 = pack2(a.x, a.x);
            ull a1 = pack2(a.y, a.y);
            ull a2 = pack2(a.z, a.z);
            ull a3 = pack2(a.w, a.w);
            ffma2(accP[0][0], a0, bv.x); ffma2(accP[0][1], a0, bv.y);
            ffma2(accP[1][0], a1, bv.x); ffma2(accP[1][1], a1, bv.y);
            ffma2(accP[2][0], a2, bv.x); ffma2(accP[2][1], a2, bv.y);
            ffma2(accP[3][0], a3, bv.x); ffma2(accP[3][1], a3, bv.y);
        }
    }
    // unpack back to round-1 float accumulators, epilogue identical to round 1
    float acc[4][4];
#pragma unroll
    for (int i = 0; i < 4; i++) {
        unpack2(accP[i][0], acc[i][0], acc[i][1]);
        unpack2(accP[i][1], acc[i][2], acc[i][3]);
    }
    float4 bv = *(const float4*)(bias + n0 + tx * 4);
#pragma unroll
    for (int i = 0; i < 4; i++) {
        float4 o;
        o.x = acc[i][0] + bv.x;
        o.y = acc[i][1] + bv.y;
        o.z = acc[i][2] + bv.z;
        o.w = acc[i][3] + bv.w;
        *(float4*)&C[(size_t)(m0 + ty * 4 + i) * N + n0 + tx * 4] = o;
    }
}

// ---------------- persistent LSTM layer (round-1 structure) ----------------
// 128 CTAs, each owns 4 hidden cols (16 gate cols). z = xw[:,t,:] + h@Wh.
// SMEM: h_s[512][64] staged per step, w_s[512][16] loaded once, c state persistent.
// Inner matmul uses fma.rn.f32x2; unpacked to float immediately after so the
// reduction + epilogue are byte-identical to the passing round-1 kernel.
__global__ void __launch_bounds__(256, 1) lstm_persistent(const float* __restrict__ xw,
                                                          const float* __restrict__ Wh,
                                                          float* __restrict__ hseqT)
{
    extern __shared__ float sm[];
    float* h_s = sm;                 // 512*64 = 32768
    float* w_s = sm + 32768;         // 512*16 =  8192
    float* red = w_s + 8192;         // 3*64*16 = 3072
    float* z_s = red + 3072;         // 64*16  =  1024
    float* c_s = z_s + 1024;         // 64*4   =   256

    const int tid = threadIdx.x;
    const int hc0 = blockIdx.x * 4;

    // load Wh slice: w_s[k][g*4+c] = Wh[k][g*512 + hc0 + c]
    for (int i = tid; i < 512 * 4; i += 256) {
        int k = i >> 2, g = i & 3;
        *(float4*)(w_s + k * 16 + g * 4) =
            *(const float4*)(Wh + (size_t)k * G_ + g * H_ + hc0);
    }
    c_s[tid] = 0.f;
    {   // zero h buf0 (this CTA's slice)
        int c = tid >> 6, b = tid & 63;
        g_hbufT[(hc0 + c) * B_ + b] = 0.f;
    }
    __threadfence();
    grid_barrier();

    const int q  = tid >> 6;   // k-split group (K range [q*128, q*128+128))
    const int r  = tid & 63;
    const int rg = r & 15;     // batch rows 4*rg .. 4*rg+3
    const int cg = r >> 4;     // gate index 0..3 (tile cols 4*cg..4*cg+3)

    for (int t = 0; t < T_; t++) {
        const float* hsrc = g_hbufT + (t & 1) * (H_ * B_);
        float*       hdst = g_hbufT + ((t & 1) ^ 1) * (H_ * B_);

        // stage full h (transposed: h_s[k][b]) from global
        for (int i = tid; i < (H_ * B_) / 4; i += 256)
            ((float4*)h_s)[i] = ((const float4*)hsrc)[i];

        // prefetch xw for this step (q==0 threads only)
        float4 xv0, xv1, xv2, xv3;
        if (q == 0) {
            const float* xp = xw + (size_t)(4 * rg * T_ + t) * G_ + cg * H_ + hc0;
            xv0 = *(const float4*)(xp);
            xv1 = *(const float4*)(xp + (size_t)T_ * G_);
            xv2 = *(const float4*)(xp + (size_t)2 * T_ * G_);
            xv3 = *(const float4*)(xp + (size_t)3 * T_ * G_);
        }
        __syncthreads();

        ull accP[4][2];
#pragma unroll
        for (int i = 0; i < 4; i++) { accP[i][0] = 0ull; accP[i][1] = 0ull; }

        const float* hp = h_s + q * 128 * 64 + 4 * rg;
        const float* wp = w_s + q * 128 * 16 + 4 * cg;
#pragma unroll 8
        for (int kk = 0; kk < 128; kk++) {
            float4 hv = *(const float4*)(hp + kk * 64);
            ulonglong2 wv = *(const ulonglong2*)(wp + kk * 16);
            ull h0 = pack2(hv.x, hv.x);
            ull h1 = pack2(hv.y, hv.y);
            ull h2 = pack2(hv.z, hv.z);
            ull h3 = pack2(hv.w, hv.w);
            ffma2(accP[0][0], h0, wv.x); ffma2(accP[0][1], h0, wv.y);
            ffma2(accP[1][0], h1, wv.x); ffma2(accP[1][1], h1, wv.y);
            ffma2(accP[2][0], h2, wv.x); ffma2(accP[2][1], h2, wv.y);
            ffma2(accP[3][0], h3, wv.x); ffma2(accP[3][1], h3, wv.y);
        }

        // unpack to round-1 float accumulators; everything below is round-1 verbatim
        float acc[4][4];
#pragma unroll
        for (int i = 0; i < 4; i++) {
            unpack2(accP[i][0], acc[i][0], acc[i][1]);
            unpack2(accP[i][1], acc[i][2], acc[i][3]);
        }

        if (q) {
            float* rp = red + ((q - 1) * 64 + r) * 16;
#pragma unroll
            for (int i = 0; i < 4; i++)
#pragma unroll
                for (int j = 0; j < 4; j++) rp[i * 4 + j] = acc[i][j];
        }
        __syncthreads();

        if (q == 0) {
#pragma unroll
            for (int qq = 0; qq < 3; qq++) {
                const float* rp = red + (qq * 64 + r) * 16;
#pragma unroll
                for (int i = 0; i < 4; i++)
#pragma unroll
                    for (int j = 0; j < 4; j++) acc[i][j] += rp[i * 4 + j];
            }
            float4 xv[4] = {xv0, xv1, xv2, xv3};
#pragma unroll
            for (int i = 0; i < 4; i++) {
                const float* xf = (const float*)&xv[i];
#pragma unroll
                for (int j = 0; j < 4; j++)
                    z_s[(4 * rg + i) * 16 + 4 * cg + j] = acc[i][j] + xf[j];
            }
        }
        __syncthreads();

        // state update: thread -> (b = tid>>2, c = tid&3)
        {
            const int b = tid >> 2, c = tid & 3;
            float zi = z_s[b * 16 + 0  + c];
            float zf = z_s[b * 16 + 4  + c];
            float zg = z_s[b * 16 + 8  + c];
            float zo = z_s[b * 16 + 12 + c];
            float ig = 1.f / (1.f + expf(-zi));
            float fg = 1.f / (1.f + expf(-zf));
            float gg = tanhf(zg);
            float og = 1.f / (1.f + expf(-zo));
            float cc = fmaf(fg, c_s[tid], ig * gg);
            c_s[tid] = cc;
            float hh = og * tanhf(cc);
            hdst[(hc0 + c) * B_ + b] = hh;
            if (hseqT)
                hseqT[(size_t)(hc0 + c) * M_ + b * T_ + t] = hh;
        }
        __threadfence();
        grid_barrier();
    }
}

// ---------------- head: out[b] = relu(relu(h@Wd1 + bd1) @ Wd2 + bd2) ----------------
__global__ void __launch_bounds__(256) head_kernel(const float* __restrict__ Wd1,
                                                   const float* __restrict__ bd1,
                                                   const float* __restrict__ Wd2,
                                                   const float* __restrict__ bd2,
                                                   float* __restrict__ out)
{
    const int b = blockIdx.x;
    const int j = threadIdx.x;                 // 0..255
    const float* hT = g_hbufT;                 // final h lives in buf0 (t=511 writes buf0)
    float acc = 0.f;
#pragma unroll 8
    for (int k = 0; k < H_; k++)
        acc = fmaf(hT[k * B_ + b], Wd1[k * (H_ / 2) + j], acc);
    float t1 = fmaxf(acc + bd1[j], 0.f);
    float p  = t1 * Wd2[j];
    __shared__ float s[256];
    s[j] = p;
    __syncthreads();
    for (int off = 128; off; off >>= 1) {
        if (j < off) s[j] += s[j + off];
        __syncthreads();
    }
    if (j == 0) out[b] = fmaxf(s[0] + bd2[0], 0.f);
}

// ---------------- launch ----------------
extern "C" void kernel_launch(void* const* d_in, const int* in_sizes, int n_in,
                              void* d_out, int out_size)
{
    (void)in_sizes; (void)n_in; (void)out_size;
    const float* x   = (const float*)d_in[0];
    // d_in[1] = training (unused)
    const float* Wi1 = (const float*)d_in[2];
    const float* Wh1 = (const float*)d_in[3];
    const float* b1  = (const float*)d_in[4];
    const float* Wi2 = (const float*)d_in[5];
    const float* Wh2 = (const float*)d_in[6];
    const float* b2  = (const float*)d_in[7];
    const float* Wd1 = (const float*)d_in[8];
    const float* bd1 = (const float*)d_in[9];
    const float* Wd2 = (const float*)d_in[10];
    const float* bd2 = (const float*)d_in[11];
    float* out = (float*)d_out;

    float *xT, *xwb, *hseqT;
    cudaGetSymbolAddress((void**)&xT,    g_xT);
    cudaGetSymbolAddress((void**)&xwb,   g_xw);
    cudaGetSymbolAddress((void**)&hseqT, g_hseqT);

    const size_t smem = (32768 + 8192 + 3072 + 1024 + 256) * sizeof(float); // 181248 B
    cudaFuncSetAttribute(lstm_persistent,
                         cudaFuncAttributeMaxDynamicSharedMemorySize, (int)smem);

    transpose_x<<<dim3(1024, 2), dim3(32, 8)>>>(x, xT);
    gemm_atb<<<dim3(G_ / 64, M_ / 64), 256>>>(xT, Wi1, b1, xwb, M_, G_, F_);
    lstm_persistent<<<NCTA_, 256, smem>>>(xwb, Wh1, hseqT);
    gemm_atb<<<dim3(G_ / 64, M_ / 64), 256>>>(hseqT, Wi2, b2, xwb, M_, G_, H_);
    lstm_persistent<<<NCTA_, 256, smem>>>(xwb, Wh2, nullptr);
    head_kernel<<<B_, 256>>>(Wd1, bd1, Wd2, bd2, out);
}